// round 5
// baseline (speedup 1.0000x reference)
#include <cuda_runtime.h>

#define B_DIM 512
#define IN_DIM 512
#define OUT_DIM 1024
#define TM 32
#define TN 64
#define TK 32

// Tropical (min-plus) matmul: out[m, n] = min_k (x[m,k] + w[n,k])
// x: [512, 512], w: [1024, 512], out: [512, 1024], row-major fp32.
//
// CTA tile 32(m) x 64(n), 128 threads, 4x4 register tile per thread.
// Grid = 16 x 16 = 256 CTAs. Double-buffered smem (one barrier per k-tile),
// register-prefetched global loads, XOR-swizzled k-major shared tiles
// (col = row ^ (k & 28)) so STS and float4 LDS are both conflict-free.
// NOTE: every swizzled column is computed as (row ^ lk) directly — the
// additive shortcut ((row0^lk)+delta) is only valid when lk has no bits in
// common with delta, which does NOT hold for delta=16 here.
__global__ __launch_bounds__(128, 2)
void tropical_mm_kernel(const float* __restrict__ x,
                        const float* __restrict__ w,
                        float* __restrict__ out)
{
    __shared__ float xs[2][TK][TM];  // xs[p][k][m ^ (k&28)]
    __shared__ float ws[2][TK][TN];  // ws[p][k][n ^ (k&28)]

    const int tid = threadIdx.x;
    const int tx = tid & 15;      // n-group: 4 outputs -> 64
    const int ty = tid >> 4;      // m-group: 4 outputs -> 32
    const int m0 = blockIdx.y * TM;
    const int n0 = blockIdx.x * TN;

    // Cooperative-load coords (float4 granularity)
    const int lr = tid >> 3;         // 0..15
    const int lk = (tid & 7) << 2;   // 0,4,...,28

    const float* xg0 = &x[(m0 + lr) * IN_DIM + lk];        // rows lr, lr+16
    const float* wg0 = &w[(n0 + lr) * IN_DIM + lk];        // rows lr,+16,+32,+48

    const float INF = __int_as_float(0x7f800000);
    float acc[4][4];
#pragma unroll
    for (int i = 0; i < 4; i++)
#pragma unroll
        for (int j = 0; j < 4; j++) acc[i][j] = INF;

    // Prologue: first tile into registers
    float4 xa0 = *reinterpret_cast<const float4*>(xg0);
    float4 xa1 = *reinterpret_cast<const float4*>(xg0 + 16 * IN_DIM);
    float4 wa0 = *reinterpret_cast<const float4*>(wg0);
    float4 wa1 = *reinterpret_cast<const float4*>(wg0 + 16 * IN_DIM);
    float4 wa2 = *reinterpret_cast<const float4*>(wg0 + 32 * IN_DIM);
    float4 wa3 = *reinterpret_cast<const float4*>(wg0 + 48 * IN_DIM);

    int p = 0;
    for (int k0 = 0; k0 < IN_DIM; k0 += TK) {
        // STS current tile into buffer p (scalar, swizzled, conflict-free).
        // All columns computed as (row ^ lk) directly.
        {
            int x0c = (lr +  0) ^ lk;
            int x1c = (lr + 16) ^ lk;
#pragma unroll
            for (int j = 0; j < 4; j++) {
                xs[p][lk + j][x0c] = (&xa0.x)[j];
                xs[p][lk + j][x1c] = (&xa1.x)[j];
            }
            int w0c = (lr +  0) ^ lk;
            int w1c = (lr + 16) ^ lk;
            int w2c = (lr + 32) ^ lk;
            int w3c = (lr + 48) ^ lk;
#pragma unroll
            for (int j = 0; j < 4; j++) {
                ws[p][lk + j][w0c] = (&wa0.x)[j];
                ws[p][lk + j][w1c] = (&wa1.x)[j];
                ws[p][lk + j][w2c] = (&wa2.x)[j];
                ws[p][lk + j][w3c] = (&wa3.x)[j];
            }
        }
        __syncthreads();

        // Prefetch next tile (overlaps the 32-k compute loop)
        if (k0 + TK < IN_DIM) {
            xg0 += TK; wg0 += TK;
            xa0 = *reinterpret_cast<const float4*>(xg0);
            xa1 = *reinterpret_cast<const float4*>(xg0 + 16 * IN_DIM);
            wa0 = *reinterpret_cast<const float4*>(wg0);
            wa1 = *reinterpret_cast<const float4*>(wg0 + 16 * IN_DIM);
            wa2 = *reinterpret_cast<const float4*>(wg0 + 32 * IN_DIM);
            wa3 = *reinterpret_cast<const float4*>(wg0 + 48 * IN_DIM);
        }

        // Compute: 8 k-classes x 4 k each. Base pointers computed once per
        // class; inner LDS are [Rbase + immediate].
#pragma unroll
        for (int i = 0; i < 8; i++) {
            const float* xp = &xs[p][i << 2][(ty << 2) ^ (i << 2)];
            const float* wp = &ws[p][i << 2][(tx << 2) ^ (i << 2)];
#pragma unroll
            for (int kk = 0; kk < 4; kk++) {
                float4 xv = *reinterpret_cast<const float4*>(xp + kk * TM);
                float4 wv = *reinterpret_cast<const float4*>(wp + kk * TN);
                float xm[4] = {xv.x, xv.y, xv.z, xv.w};
                float wn[4] = {wv.x, wv.y, wv.z, wv.w};
#pragma unroll
                for (int a = 0; a < 4; a++)
#pragma unroll
                    for (int b = 0; b < 4; b++)
                        acc[a][b] = fminf(acc[a][b], xm[a] + wn[b]);
            }
        }
        p ^= 1;
        // Single barrier per tile is safe: before any thread can overwrite
        // buffer q, it must pass the barrier of the *following* tile, which
        // happens after every thread finished computing from q.
    }

    // Epilogue: 4 rows of float4 per thread
#pragma unroll
    for (int i = 0; i < 4; i++) {
        float4 o = make_float4(acc[i][0], acc[i][1], acc[i][2], acc[i][3]);
        *reinterpret_cast<float4*>(&out[(m0 + (ty << 2) + i) * OUT_DIM + n0 + (tx << 2)]) = o;
    }
}

extern "C" void kernel_launch(void* const* d_in, const int* in_sizes, int n_in,
                              void* d_out, int out_size)
{
    const float* x = (const float*)d_in[0];   // [512, 512]
    const float* w = (const float*)d_in[1];   // [1024, 512]
    float* out = (float*)d_out;               // [512, 1024]

    dim3 grid(OUT_DIM / TN, B_DIM / TM);      // (16, 16) = 256 CTAs
    dim3 block(128);
    tropical_mm_kernel<<<grid, block>>>(x, w, out);
}

// round 6
// speedup vs baseline: 1.0743x; 1.0743x over previous
#include <cuda_runtime.h>
#include <cstdint>

#define B_DIM 512
#define IN_DIM 512
#define OUT_DIM 1024
#define TM 32
#define TN 64
#define TK 32

// Tropical (min-plus) matmul: out[m, n] = min_k (x[m,k] + w[n,k])
// x: [512, 512], w: [1024, 512], out: [512, 1024], row-major fp32.
//
// CTA tile 32(m) x 64(n), 128 threads, 4x4 register tile per thread.
// Grid = 256 CTAs, up to 4 CTAs/SM resident (16 warps/SM) for latency hiding.
// Double-buffered XOR-swizzled k-major smem tiles (col = row ^ (k & 28)),
// one barrier per k-tile, register-prefetched global loads.
// Adds are packed 2-wide via add.rn.f32x2 (Blackwell packed fp32, RN —
// bitwise identical to scalar FADD); mins stay scalar FMNMX.

__device__ __forceinline__ unsigned long long pack2(float lo, float hi) {
    unsigned long long r;
    asm("mov.b64 %0, {%1, %2};" : "=l"(r) : "r"(__float_as_uint(lo)), "r"(__float_as_uint(hi)));
    return r;
}
__device__ __forceinline__ unsigned long long addf32x2(unsigned long long a, unsigned long long b) {
    unsigned long long r;
    asm("add.rn.f32x2 %0, %1, %2;" : "=l"(r) : "l"(a), "l"(b));
    return r;
}
__device__ __forceinline__ void unpack2(unsigned long long v, float& lo, float& hi) {
    uint32_t l, h;
    asm("mov.b64 {%0, %1}, %2;" : "=r"(l), "=r"(h) : "l"(v));
    lo = __uint_as_float(l);
    hi = __uint_as_float(h);
}

__global__ __launch_bounds__(128, 4)
void tropical_mm_kernel(const float* __restrict__ x,
                        const float* __restrict__ w,
                        float* __restrict__ out)
{
    __shared__ float xs[2][TK][TM];  // xs[p][k][m ^ (k&28)]
    __shared__ float ws[2][TK][TN];  // ws[p][k][n ^ (k&28)]

    const int tid = threadIdx.x;
    const int tx = tid & 15;      // n-group: 4 outputs -> 64
    const int ty = tid >> 4;      // m-group: 4 outputs -> 32
    const int m0 = blockIdx.y * TM;
    const int n0 = blockIdx.x * TN;

    // Cooperative-load coords (float4 granularity)
    const int lr = tid >> 3;         // 0..15
    const int lk = (tid & 7) << 2;   // 0,4,...,28

    const float* xg0 = &x[(m0 + lr) * IN_DIM + lk];
    const float* wg0 = &w[(n0 + lr) * IN_DIM + lk];

    const float INF = __int_as_float(0x7f800000);
    float acc[4][4];
#pragma unroll
    for (int i = 0; i < 4; i++)
#pragma unroll
        for (int j = 0; j < 4; j++) acc[i][j] = INF;

    // Prologue: first tile into registers
    float4 xa0 = *reinterpret_cast<const float4*>(xg0);
    float4 xa1 = *reinterpret_cast<const float4*>(xg0 + 16 * IN_DIM);
    float4 wa0 = *reinterpret_cast<const float4*>(wg0);
    float4 wa1 = *reinterpret_cast<const float4*>(wg0 + 16 * IN_DIM);
    float4 wa2 = *reinterpret_cast<const float4*>(wg0 + 32 * IN_DIM);
    float4 wa3 = *reinterpret_cast<const float4*>(wg0 + 48 * IN_DIM);

    int p = 0;
    for (int k0 = 0; k0 < IN_DIM; k0 += TK) {
        // STS current tile (swizzled, conflict-free). Columns computed as
        // (row ^ lk) directly — NO additive shortcuts (see R3 bug).
        {
            int x0c = (lr +  0) ^ lk;
            int x1c = (lr + 16) ^ lk;
#pragma unroll
            for (int j = 0; j < 4; j++) {
                xs[p][lk + j][x0c] = (&xa0.x)[j];
                xs[p][lk + j][x1c] = (&xa1.x)[j];
            }
            int w0c = (lr +  0) ^ lk;
            int w1c = (lr + 16) ^ lk;
            int w2c = (lr + 32) ^ lk;
            int w3c = (lr + 48) ^ lk;
#pragma unroll
            for (int j = 0; j < 4; j++) {
                ws[p][lk + j][w0c] = (&wa0.x)[j];
                ws[p][lk + j][w1c] = (&wa1.x)[j];
                ws[p][lk + j][w2c] = (&wa2.x)[j];
                ws[p][lk + j][w3c] = (&wa3.x)[j];
            }
        }
        __syncthreads();

        // Prefetch next tile (overlaps the 32-k compute loop)
        if (k0 + TK < IN_DIM) {
            xg0 += TK; wg0 += TK;
            xa0 = *reinterpret_cast<const float4*>(xg0);
            xa1 = *reinterpret_cast<const float4*>(xg0 + 16 * IN_DIM);
            wa0 = *reinterpret_cast<const float4*>(wg0);
            wa1 = *reinterpret_cast<const float4*>(wg0 + 16 * IN_DIM);
            wa2 = *reinterpret_cast<const float4*>(wg0 + 32 * IN_DIM);
            wa3 = *reinterpret_cast<const float4*>(wg0 + 48 * IN_DIM);
        }

        // Compute: 8 k-classes x 4 k each; base pointers computed once per
        // class, inner LDS are [Rbase + immediate].
#pragma unroll
        for (int i = 0; i < 8; i++) {
            const float* xp = &xs[p][i << 2][(ty << 2) ^ (i << 2)];
            const float* wp = &ws[p][i << 2][(tx << 2) ^ (i << 2)];
#pragma unroll
            for (int kk = 0; kk < 4; kk++) {
                float4 xv = *reinterpret_cast<const float4*>(xp + kk * TM);
                float4 wv = *reinterpret_cast<const float4*>(wp + kk * TN);
                // w pairs: consecutive LDS.128 result regs -> pack is a rename
                unsigned long long w01 = pack2(wv.x, wv.y);
                unsigned long long w23 = pack2(wv.z, wv.w);
#pragma unroll
                for (int a = 0; a < 4; a++) {
                    float xa = (&xv.x)[a];
                    unsigned long long xd = pack2(xa, xa);
                    unsigned long long s01 = addf32x2(xd, w01);
                    unsigned long long s23 = addf32x2(xd, w23);
                    float s0, s1, s2, s3;
                    unpack2(s01, s0, s1);
                    unpack2(s23, s2, s3);
                    acc[a][0] = fminf(acc[a][0], s0);
                    acc[a][1] = fminf(acc[a][1], s1);
                    acc[a][2] = fminf(acc[a][2], s2);
                    acc[a][3] = fminf(acc[a][3], s3);
                }
            }
        }
        p ^= 1;
        // Single barrier per tile: nobody can overwrite buffer q before
        // passing the next tile's barrier, by which time all threads have
        // finished computing from q.
    }

    // Epilogue: 4 rows of float4 per thread
#pragma unroll
    for (int i = 0; i < 4; i++) {
        float4 o = make_float4(acc[i][0], acc[i][1], acc[i][2], acc[i][3]);
        *reinterpret_cast<float4*>(&out[(m0 + (ty << 2) + i) * OUT_DIM + n0 + (tx << 2)]) = o;
    }
}

extern "C" void kernel_launch(void* const* d_in, const int* in_sizes, int n_in,
                              void* d_out, int out_size)
{
    const float* x = (const float*)d_in[0];   // [512, 512]
    const float* w = (const float*)d_in[1];   // [1024, 512]
    float* out = (float*)d_out;               // [512, 1024]

    dim3 grid(OUT_DIM / TN, B_DIM / TM);      // (16, 16) = 256 CTAs
    dim3 block(128);
    tropical_mm_kernel<<<grid, block>>>(x, w, out);
}